// round 8
// baseline (speedup 1.0000x reference)
#include <cuda_runtime.h>
#include <cuda_fp16.h>
#include <math.h>
#include <stdint.h>

#define NN      100000
#define EE      800000
#define IN_DIM  128
#define HID     256
#define OUT_DIM 256
#define GG      2048

#define SCAN_BLK 1024
#define NB_SCAN  ((NN + SCAN_BLK - 1) / SCAN_BLK)   // 98

// fused prep kernel ranges
#define XQ      (NN * IN_DIM / 4)           // 3,200,000 x-quads
#define W1E     (256 * IN_DIM)              // 32768
#define W2E     (256 * HID)                 // 65536
#define W3E     (256 * HID)                 // 65536
#define PREP_T  (XQ + W1E + W2E + W3E + EE) // total threads

// ---------------- scratch (device globals; no allocation allowed) -----------
__device__ __half g_bufAh[(size_t)NN * HID];
__device__ __half g_bufBh[(size_t)NN * HID];
__device__ __half g_xh[(size_t)NN * IN_DIM];
__device__ __half g_w1h[256 * IN_DIM];    // [n][k] transposed
__device__ __half g_w2h[256 * HID];
__device__ __half g_w3h[256 * HID];
__device__ __half g_poolh[(size_t)GG * OUT_DIM];
__device__ float  g_dis[NN];
__device__ int    g_deg[NN];    // zero at load; re-zeroed in k_fill each launch
__device__ int    g_cur0[NN];   // zero at load; re-zeroed in k_agg_h<128>
__device__ int    g_rowptr[NN]; // block-local exclusive scan
__device__ int    g_rowf[NN + 1]; // final CSR row pointers
__device__ int    g_csrc[EE];
__device__ float  g_cnorm[EE];
__device__ int    g_bsum[NB_SCAN];
__device__ float  g_maskf[GG];

// ---------------- helpers ---------------------------------------------------
__device__ __forceinline__ uint32_t smem_u32(const void* p) {
    uint32_t a;
    asm("{ .reg .u64 t; cvta.to.shared.u64 t, %1; cvt.u32.u64 %0, t; }"
        : "=r"(a) : "l"(p));
    return a;
}

__device__ __forceinline__ void cp16(uint32_t dst, const void* src, int src_sz) {
    asm volatile("cp.async.cg.shared.global [%0], [%1], 16, %2;"
                 :: "r"(dst), "l"(src), "r"(src_sz));
}

__device__ __forceinline__ void mma_f16(float* c, const uint32_t* a, const uint32_t* b) {
    asm volatile(
        "mma.sync.aligned.m16n8k16.row.col.f32.f16.f16.f32 "
        "{%0,%1,%2,%3}, {%4,%5,%6,%7}, {%8,%9}, {%0,%1,%2,%3};"
        : "+f"(c[0]), "+f"(c[1]), "+f"(c[2]), "+f"(c[3])
        : "r"(a[0]), "r"(a[1]), "r"(a[2]), "r"(a[3]), "r"(b[0]), "r"(b[1]));
}

__device__ __forceinline__ void ldmx4(uint32_t* r, uint32_t addr) {
    asm volatile("ldmatrix.sync.aligned.m8n8.x4.shared.b16 {%0,%1,%2,%3}, [%4];"
                 : "=r"(r[0]), "=r"(r[1]), "=r"(r[2]), "=r"(r[3]) : "r"(addr));
}

// ---------------- fused prep: cvt x + 3 weight transposes + degree hist -----
// edge_index / batch arrive as INT32 (JAX x64-disabled)
__global__ void k_prep(const float* __restrict__ x,
                       const float* __restrict__ W1,
                       const float* __restrict__ W2,
                       const float* __restrict__ W3,
                       const int* __restrict__ ei) {
    int i = blockIdx.x * blockDim.x + threadIdx.x;
    if (i < XQ) {
        float4 v = ((const float4*)x)[i];
        __half2 h0 = __floats2half2_rn(v.x, v.y);
        __half2 h1 = __floats2half2_rn(v.z, v.w);
        uint2 u;
        u.x = *(uint32_t*)&h0;
        u.y = *(uint32_t*)&h1;
        ((uint2*)g_xh)[i] = u;
    } else if (i < XQ + W1E) {
        int j = i - XQ;
        int n = j >> 7, k = j & 127;
        g_w1h[j] = __float2half(W1[(size_t)k * 256 + n]);
    } else if (i < XQ + W1E + W2E) {
        int j = i - XQ - W1E;
        int n = j >> 8, k = j & 255;
        g_w2h[j] = __float2half(W2[(size_t)k * 256 + n]);
    } else if (i < XQ + W1E + W2E + W3E) {
        int j = i - XQ - W1E - W2E;
        int n = j >> 8, k = j & 255;
        g_w3h[j] = __float2half(W3[(size_t)k * 256 + n]);
    } else if (i < PREP_T) {
        int e = i - XQ - W1E - W2E - W3E;
        atomicAdd(&g_deg[ei[EE + e]], 1);
    }
}

// ---------------- scan phase 1 (+dis) and phase 2 ---------------------------
__global__ void k_scan1() {
    __shared__ int s[SCAN_BLK];
    int tid = threadIdx.x;
    int i = blockIdx.x * SCAN_BLK + tid;
    int v = 0;
    if (i < NN) {
        v = g_deg[i];
        g_dis[i] = rsqrtf((float)(v + 1));   // +1 self loop
    }
    s[tid] = v;
    __syncthreads();
    for (int off = 1; off < SCAN_BLK; off <<= 1) {
        int t = (tid >= off) ? s[tid - off] : 0;
        __syncthreads();
        s[tid] += t;
        __syncthreads();
    }
    if (i < NN) g_rowptr[i] = s[tid] - v;
    if (tid == SCAN_BLK - 1) g_bsum[blockIdx.x] = s[tid];
}

__global__ void k_scan2() {
    if (threadIdx.x == 0) {
        int acc = 0;
        for (int b = 0; b < NB_SCAN; b++) {
            int t = g_bsum[b];
            g_bsum[b] = acc;
            acc += t;
        }
    }
}

// ---------------- CSR fill (absorbs old scan3) ------------------------------
// g_cur0 is zero on entry (reset by k_agg_h<128> after previous use).
__global__ void k_fill(const int* __restrict__ ei) {
    int e = blockIdx.x * blockDim.x + threadIdx.x;
    if (e < EE) {
        int s = ei[e];
        int d = ei[EE + e];
        int r = g_rowptr[d] + g_bsum[d >> 10];
        int p = r + atomicAdd(&g_cur0[d], 1);
        g_csrc[p]  = s;
        g_cnorm[p] = g_dis[s] * g_dis[d];
    }
    if (e < NN) {
        g_rowf[e] = g_rowptr[e] + g_bsum[e >> 10];
        g_deg[e]  = 0;                       // re-zero for next graph replay
    }
    if (e == 0) g_rowf[NN] = EE;
}

// ---------------- aggregation: warp per node, half gather, fp32 accum -------
template <int D>   // D in {128, 256}
__global__ void __launch_bounds__(256)
k_agg_h(const __half* __restrict__ in, __half* __restrict__ out) {
    constexpr int VH = D / 64;            // half2 per lane: 2 or 4
    int v    = (blockIdx.x * 256 + threadIdx.x) >> 5;
    int lane = threadIdx.x & 31;
    if (v >= NN) return;

    if (D == 128 && lane == 0) g_cur0[v] = 0;   // reset for next replay's k_fill

    float ds = g_dis[v];
    float ws = ds * ds;                   // self-loop weight

    const __half* rowv = in + (size_t)v * D + lane * (VH * 2);
    float2 a[VH];
#pragma unroll
    for (int j = 0; j < VH; j++) {
        float2 x = __half22float2(((const __half2*)rowv)[j]);
        a[j] = make_float2(ws * x.x, ws * x.y);
    }

    int beg = g_rowf[v];
    int end = g_rowf[v + 1];
    int cnt = end - beg;
    int i = beg;
    int end4 = beg + (cnt & ~3);
    for (; i < end4; i += 4) {
        int   sv[4];
        float nv[4];
        __half2 h[4][VH];
#pragma unroll
        for (int q = 0; q < 4; q++) { sv[q] = g_csrc[i + q]; nv[q] = g_cnorm[i + q]; }
#pragma unroll
        for (int q = 0; q < 4; q++) {
            const __half2* r = (const __half2*)(in + (size_t)sv[q] * D + lane * (VH * 2));
            if (VH == 4) {
                float4 u = *(const float4*)r;
                h[q][0] = *(__half2*)&u.x; h[q][1] = *(__half2*)&u.y;
                h[q][2] = *(__half2*)&u.z; h[q][3] = *(__half2*)&u.w;
            } else {
                float2 u = *(const float2*)r;
                h[q][0] = *(__half2*)&u.x; h[q][1] = *(__half2*)&u.y;
            }
        }
#pragma unroll
        for (int q = 0; q < 4; q++)
#pragma unroll
            for (int j = 0; j < VH; j++) {
                float2 y = __half22float2(h[q][j]);
                a[j].x += nv[q] * y.x;
                a[j].y += nv[q] * y.y;
            }
    }
    for (; i < end; i++) {
        int   s0 = g_csrc[i];
        float n0 = g_cnorm[i];
        const __half2* r0 = (const __half2*)(in + (size_t)s0 * D + lane * (VH * 2));
#pragma unroll
        for (int j = 0; j < VH; j++) {
            float2 y0 = __half22float2(r0[j]);
            a[j].x += n0 * y0.x;
            a[j].y += n0 * y0.y;
        }
    }

    __half2* o = (__half2*)(out + (size_t)v * D + lane * (VH * 2));
#pragma unroll
    for (int j = 0; j < VH; j++)
        o[j] = __floats2half2_rn(a[j].x, a[j].y);
}

// ---------------- fp16 tensor-core GEMM, cp.async + ldmatrix ----------------
// C[M,256] = act(A[M,K] @ Wt^T + bias) [* mask[row]]
template <bool RELU, bool MASK, bool HALF_OUT>
__global__ void __launch_bounds__(256, 2)
k_gemm_h(const __half* __restrict__ A, const __half* __restrict__ Wt,
         const float* __restrict__ bias, const float* __restrict__ mask,
         void* __restrict__ Cout, int M, int K) {
    __shared__ __half As[2][128][40];   // [m][k], 80B rows -> conflict-free
    __shared__ __half Bs[2][128][40];   // [n][k]

    int tid  = threadIdx.x;
    int wid  = tid >> 5;
    int lane = tid & 31;
    int g    = lane >> 2;           // 0..7
    int tig  = lane & 3;            // 0..3
    int warp_m = wid & 1;
    int warp_n = wid >> 1;
    int brow = blockIdx.y * 128;
    int bcol = blockIdx.x * 128;

    float acc[4][4][4];
#pragma unroll
    for (int i = 0; i < 4; i++)
#pragma unroll
        for (int j = 0; j < 4; j++)
#pragma unroll
            for (int l = 0; l < 4; l++) acc[i][j][l] = 0.f;

    int lr  = tid >> 2;             // 0..63 (+64 on l=1)
    int lc8 = (tid & 3) << 3;       // k-offset 0,8,16,24 halves

    auto load_tiles = [&](int s, int k0) {
#pragma unroll
        for (int l = 0; l < 2; l++) {
            int r = lr + l * 64;
            int row = brow + r;
            cp16(smem_u32(&As[s][r][lc8]),
                 A + (size_t)row * K + k0 + lc8, row < M ? 16 : 0);
            cp16(smem_u32(&Bs[s][r][lc8]),
                 Wt + (size_t)(bcol + r) * K + k0 + lc8, 16);
        }
        asm volatile("cp.async.commit_group;");
    };

    int a_r  = lane & 15;
    int a_c8 = (lane & 16) >> 1;
    int b_r  = ((lane & 16) >> 1) + (lane & 7);
    int b_c8 = lane & 8;

    load_tiles(0, 0);
    int s = 0;
    for (int k0 = 0; k0 < K; k0 += 32) {
        if (k0 + 32 < K) load_tiles(s ^ 1, k0 + 32);
        else             asm volatile("cp.async.commit_group;");
        asm volatile("cp.async.wait_group 1;");
        __syncthreads();

#pragma unroll
        for (int ks = 0; ks < 32; ks += 16) {
            uint32_t af[4][4], bf[4][2];
#pragma unroll
            for (int mf = 0; mf < 4; mf++) {
                int m0 = warp_m * 64 + mf * 16;
                ldmx4(af[mf], smem_u32(&As[s][m0 + a_r][ks + a_c8]));
            }
#pragma unroll
            for (int p = 0; p < 2; p++) {
                int n0 = warp_n * 32 + p * 16;
                uint32_t br[4];
                ldmx4(br, smem_u32(&Bs[s][n0 + b_r][ks + b_c8]));
                bf[2 * p][0] = br[0]; bf[2 * p][1] = br[1];
                bf[2 * p + 1][0] = br[2]; bf[2 * p + 1][1] = br[3];
            }
#pragma unroll
            for (int mf = 0; mf < 4; mf++)
#pragma unroll
                for (int nf = 0; nf < 4; nf++)
                    mma_f16(acc[mf][nf], af[mf], bf[nf]);
        }
        __syncthreads();
        s ^= 1;
    }

#pragma unroll
    for (int mf = 0; mf < 4; mf++) {
        int row0 = brow + warp_m * 64 + mf * 16 + g;
        int row1 = row0 + 8;
        float mk0 = 1.f, mk1 = 1.f;
        if (MASK) {
            if (row0 < M) mk0 = mask[row0];
            if (row1 < M) mk1 = mask[row1];
        }
#pragma unroll
        for (int nf = 0; nf < 4; nf++) {
            int col = bcol + warp_n * 32 + nf * 8 + tig * 2;
            float2 bb = *(const float2*)(bias + col);
            float v0 = acc[mf][nf][0] + bb.x;
            float v1 = acc[mf][nf][1] + bb.y;
            float v2 = acc[mf][nf][2] + bb.x;
            float v3 = acc[mf][nf][3] + bb.y;
            if (RELU) {
                v0 = fmaxf(v0, 0.f); v1 = fmaxf(v1, 0.f);
                v2 = fmaxf(v2, 0.f); v3 = fmaxf(v3, 0.f);
            }
            if (HALF_OUT) {
                __half* C = (__half*)Cout;
                if (row0 < M)
                    *(__half2*)(C + (size_t)row0 * 256 + col) = __floats2half2_rn(v0, v1);
                if (row1 < M)
                    *(__half2*)(C + (size_t)row1 * 256 + col) = __floats2half2_rn(v2, v3);
            } else {
                float* C = (float*)Cout;
                if (row0 < M)
                    *(float2*)(C + (size_t)row0 * 256 + col) = make_float2(v0 * mk0, v1 * mk0);
                if (row1 < M)
                    *(float2*)(C + (size_t)row1 * 256 + col) = make_float2(v2 * mk1, v3 * mk1);
            }
        }
    }
}

// ---------------- fused layer-3 agg + global mean pool ----------------------
// batch sorted -> block per graph; thread owns one column; inline CSR gather.
__global__ void __launch_bounds__(256)
k_pool_agg(const int* __restrict__ batch, const __half* __restrict__ h) {
    int gph = blockIdx.x;
    int c   = threadIdx.x;
    __shared__ int s_lo, s_hi;
    if (c == 0) {
        int lo = 0, hi = NN;
        while (lo < hi) { int mid = (lo + hi) >> 1; if (batch[mid] < gph) lo = mid + 1; else hi = mid; }
        s_lo = lo;
    }
    if (c == 1) {
        int lo = 0, hi = NN;
        while (lo < hi) { int mid = (lo + hi) >> 1; if (batch[mid] < gph + 1) lo = mid + 1; else hi = mid; }
        s_hi = lo;
    }
    __syncthreads();
    int lo = s_lo, hi = s_hi;

    float acc = 0.f;
    for (int v = lo; v < hi; v++) {
        float ds = g_dis[v];
        acc += (ds * ds) * __half2float(h[(size_t)v * 256 + c]);
        int beg = g_rowf[v];
        int end = g_rowf[v + 1];
        for (int i = beg; i < end; i++) {
            int   s  = g_csrc[i];
            float nm = g_cnorm[i];
            acc += nm * __half2float(h[(size_t)s * 256 + c]);
        }
    }
    g_poolh[(size_t)gph * 256 + c] = __float2half(acc / fmaxf((float)(hi - lo), 1.f));
    if (c == 0) g_maskf[gph] = (hi > lo) ? 1.f : 0.f;
}

// ---------------- launch ----------------------------------------------------
extern "C" void kernel_launch(void* const* d_in, const int* in_sizes, int n_in,
                              void* d_out, int out_size) {
    const float* x     = (const float*)d_in[0];
    const float* W1    = (const float*)d_in[1];
    const float* b1    = (const float*)d_in[2];
    const float* W2    = (const float*)d_in[3];
    const float* b2    = (const float*)d_in[4];
    const float* W3    = (const float*)d_in[5];
    const float* b3    = (const float*)d_in[6];
    const int*   ei    = (const int*)d_in[7];
    const int*   batch = (const int*)d_in[8];
    float*       out   = (float*)d_out;

    __half *hA, *hB, *xh, *w1h, *w2h, *w3h, *poolh;
    float  *maskb;
    cudaGetSymbolAddress((void**)&hA,    g_bufAh);
    cudaGetSymbolAddress((void**)&hB,    g_bufBh);
    cudaGetSymbolAddress((void**)&xh,    g_xh);
    cudaGetSymbolAddress((void**)&w1h,   g_w1h);
    cudaGetSymbolAddress((void**)&w2h,   g_w2h);
    cudaGetSymbolAddress((void**)&w3h,   g_w3h);
    cudaGetSymbolAddress((void**)&poolh, g_poolh);
    cudaGetSymbolAddress((void**)&maskb, g_maskf);

    dim3 blk(256);
    int gE = (EE + 255) / 256;

    // prep + CSR build (4 launches)
    k_prep<<<(PREP_T + 255) / 256, blk>>>(x, W1, W2, W3, ei);
    k_scan1<<<NB_SCAN, SCAN_BLK>>>();
    k_scan2<<<1, 32>>>();
    k_fill<<<gE, blk>>>(ei);

    dim3 ggrid(2, (NN + 127) / 128);
    dim3 ggrid3(2, GG / 128);
    int gAgg = (NN * 32 + 255) / 256;

    // layer 1: agg in 128-dim (half), GEMM(+bias+relu) -> half
    k_agg_h<128><<<gAgg, 256>>>(xh, hA);
    k_gemm_h<true, false, true><<<ggrid, 256>>>(hA, w1h, b1, nullptr, hB, NN, IN_DIM);

    // layer 2
    k_agg_h<256><<<gAgg, 256>>>(hB, hA);
    k_gemm_h<true, false, true><<<ggrid, 256>>>(hA, w2h, b2, nullptr, hB, NN, HID);

    // layer 3: fused agg+pool, then tiny GEMM on pooled [G,256] -> float out
    k_pool_agg<<<GG, 256>>>(batch, hB);
    k_gemm_h<false, true, false><<<ggrid3, 256>>>(poolh, w3h, b3, maskb, out, GG, HID);
}

// round 10
// speedup vs baseline: 1.3553x; 1.3553x over previous
#include <cuda_runtime.h>
#include <cuda_fp16.h>
#include <math.h>
#include <stdint.h>

#define NN      100000
#define EE      800000
#define IN_DIM  128
#define HID     256
#define OUT_DIM 256
#define GG      2048

#define SCAN_BLK 1024
#define NB_SCAN  ((NN + SCAN_BLK - 1) / SCAN_BLK)   // 98

// fused prep kernel ranges
#define XQ      (NN * IN_DIM / 4)           // 3,200,000 x-quads
#define W1E     (256 * IN_DIM)              // 32768
#define W2E     (256 * HID)                 // 65536
#define W3E     (256 * HID)                 // 65536
#define PREP_T  (XQ + W1E + W2E + W3E + EE) // total threads

// ---------------- scratch (device globals; no allocation allowed) -----------
__device__ __half g_bufAh[(size_t)NN * HID];
__device__ __half g_bufBh[(size_t)NN * HID];
__device__ __half g_xh[(size_t)NN * IN_DIM];
__device__ __half g_w1h[256 * IN_DIM];    // [n][k] transposed
__device__ __half g_w2h[256 * HID];
__device__ __half g_w3h[256 * HID];
__device__ __half g_poolh[(size_t)GG * OUT_DIM];
__device__ float  g_dis[NN];
__device__ int    g_deg[NN];         // zero-init at load; re-zeroed in k_fill
__device__ int    g_rowptr[NN + 1];
__device__ int    g_cursor[NN];
__device__ int2   g_cedge[EE];       // packed (src, norm-bits)
__device__ int    g_bsum[NB_SCAN];
__device__ float  g_maskf[GG];

// ---------------- helpers ---------------------------------------------------
__device__ __forceinline__ uint32_t smem_u32(const void* p) {
    uint32_t a;
    asm("{ .reg .u64 t; cvta.to.shared.u64 t, %1; cvt.u32.u64 %0, t; }"
        : "=r"(a) : "l"(p));
    return a;
}

__device__ __forceinline__ void cp16(uint32_t dst, const void* src, int src_sz) {
    asm volatile("cp.async.cg.shared.global [%0], [%1], 16, %2;"
                 :: "r"(dst), "l"(src), "r"(src_sz));
}

__device__ __forceinline__ void mma_f16(float* c, const uint32_t* a, const uint32_t* b) {
    asm volatile(
        "mma.sync.aligned.m16n8k16.row.col.f32.f16.f16.f32 "
        "{%0,%1,%2,%3}, {%4,%5,%6,%7}, {%8,%9}, {%0,%1,%2,%3};"
        : "+f"(c[0]), "+f"(c[1]), "+f"(c[2]), "+f"(c[3])
        : "r"(a[0]), "r"(a[1]), "r"(a[2]), "r"(a[3]), "r"(b[0]), "r"(b[1]));
}

__device__ __forceinline__ void ldmx4(uint32_t* r, uint32_t addr) {
    asm volatile("ldmatrix.sync.aligned.m8n8.x4.shared.b16 {%0,%1,%2,%3}, [%4];"
                 : "=r"(r[0]), "=r"(r[1]), "=r"(r[2]), "=r"(r[3]) : "r"(addr));
}

// ---------------- fused prep: cvt x + 3 weight transposes + degree hist -----
// edge_index / batch arrive as INT32 (JAX x64-disabled)
__global__ void k_prep(const float* __restrict__ x,
                       const float* __restrict__ W1,
                       const float* __restrict__ W2,
                       const float* __restrict__ W3,
                       const int* __restrict__ ei) {
    int i = blockIdx.x * blockDim.x + threadIdx.x;
    if (i < XQ) {
        float4 v = ((const float4*)x)[i];
        __half2 h0 = __floats2half2_rn(v.x, v.y);
        __half2 h1 = __floats2half2_rn(v.z, v.w);
        uint2 u;
        u.x = *(uint32_t*)&h0;
        u.y = *(uint32_t*)&h1;
        ((uint2*)g_xh)[i] = u;
    } else if (i < XQ + W1E) {
        int j = i - XQ;
        int n = j >> 7, k = j & 127;
        g_w1h[j] = __float2half(W1[(size_t)k * 256 + n]);
    } else if (i < XQ + W1E + W2E) {
        int j = i - XQ - W1E;
        int n = j >> 8, k = j & 255;
        g_w2h[j] = __float2half(W2[(size_t)k * 256 + n]);
    } else if (i < XQ + W1E + W2E + W3E) {
        int j = i - XQ - W1E - W2E;
        int n = j >> 8, k = j & 255;
        g_w3h[j] = __float2half(W3[(size_t)k * 256 + n]);
    } else if (i < PREP_T) {
        int e = i - XQ - W1E - W2E - W3E;
        atomicAdd(&g_deg[ei[EE + e]], 1);
    }
}

// ---------------- graph-structure kernels -----------------------------------
__global__ void k_scan1() {
    __shared__ int s[SCAN_BLK];
    int tid = threadIdx.x;
    int i = blockIdx.x * SCAN_BLK + tid;
    int v = 0;
    if (i < NN) {
        v = g_deg[i];
        g_dis[i] = rsqrtf((float)(v + 1));   // +1 self loop
    }
    s[tid] = v;
    __syncthreads();
    for (int off = 1; off < SCAN_BLK; off <<= 1) {
        int t = (tid >= off) ? s[tid - off] : 0;
        __syncthreads();
        s[tid] += t;
        __syncthreads();
    }
    if (i < NN) g_rowptr[i] = s[tid] - v;
    if (tid == SCAN_BLK - 1) g_bsum[blockIdx.x] = s[tid];
}

// exclusive scan of the 98 block sums (one 128-thread block)
__global__ void k_scan2() {
    __shared__ int s[128];
    int t = threadIdx.x;
    int v = (t < NB_SCAN) ? g_bsum[t] : 0;
    s[t] = v;
    __syncthreads();
    for (int off = 1; off < 128; off <<= 1) {
        int u = (t >= off) ? s[t - off] : 0;
        __syncthreads();
        s[t] += u;
        __syncthreads();
    }
    if (t < NB_SCAN) g_bsum[t] = s[t] - v;   // exclusive
}

__global__ void k_scan3() {
    int i = blockIdx.x * blockDim.x + threadIdx.x;
    if (i < NN) {
        int r = g_rowptr[i] + g_bsum[i / SCAN_BLK];
        g_rowptr[i] = r;
        g_cursor[i] = r;
    }
    if (i == 0) g_rowptr[NN] = EE;
}

__global__ void k_fill(const int* __restrict__ ei) {
    int e = blockIdx.x * blockDim.x + threadIdx.x;
    if (e < EE) {
        int s = ei[e];
        int d = ei[EE + e];
        int p = atomicAdd(&g_cursor[d], 1);
        g_cedge[p] = make_int2(s, __float_as_int(g_dis[s] * g_dis[d]));
    }
    if (e < NN) g_deg[e] = 0;   // re-zero for next graph replay
}

// ---------------- aggregation: warp per node, half gather, fp32 accum -------
template <int D>   // D in {128, 256}
__global__ void __launch_bounds__(256)
k_agg_h(const __half* __restrict__ in, __half* __restrict__ out) {
    constexpr int VH = D / 64;            // half2 per lane: 2 or 4
    int v    = (blockIdx.x * 256 + threadIdx.x) >> 5;
    int lane = threadIdx.x & 31;
    if (v >= NN) return;

    float ds = g_dis[v];
    float ws = ds * ds;                   // self-loop weight

    const __half* rowv = in + (size_t)v * D + lane * (VH * 2);
    float2 a[VH];
#pragma unroll
    for (int j = 0; j < VH; j++) {
        float2 x = __half22float2(((const __half2*)rowv)[j]);
        a[j] = make_float2(ws * x.x, ws * x.y);
    }

    int beg = g_rowptr[v];
    int end = g_rowptr[v + 1];
    int cnt = end - beg;
    int i = beg;
    int end4 = beg + (cnt & ~3);
    for (; i < end4; i += 4) {
        int2 ev[4];
        __half2 h[4][VH];
#pragma unroll
        for (int q = 0; q < 4; q++) ev[q] = g_cedge[i + q];
#pragma unroll
        for (int q = 0; q < 4; q++) {
            const __half2* r = (const __half2*)(in + (size_t)ev[q].x * D + lane * (VH * 2));
            if (VH == 4) {
                float4 u = *(const float4*)r;
                h[q][0] = *(__half2*)&u.x; h[q][1] = *(__half2*)&u.y;
                h[q][2] = *(__half2*)&u.z; h[q][3] = *(__half2*)&u.w;
            } else {
                float2 u = *(const float2*)r;
                h[q][0] = *(__half2*)&u.x; h[q][1] = *(__half2*)&u.y;
            }
        }
#pragma unroll
        for (int q = 0; q < 4; q++) {
            float nv = __int_as_float(ev[q].y);
#pragma unroll
            for (int j = 0; j < VH; j++) {
                float2 y = __half22float2(h[q][j]);
                a[j].x += nv * y.x;
                a[j].y += nv * y.y;
            }
        }
    }
    for (; i < end; i++) {
        int2 ev = g_cedge[i];
        float n0 = __int_as_float(ev.y);
        const __half2* r0 = (const __half2*)(in + (size_t)ev.x * D + lane * (VH * 2));
#pragma unroll
        for (int j = 0; j < VH; j++) {
            float2 y0 = __half22float2(r0[j]);
            a[j].x += n0 * y0.x;
            a[j].y += n0 * y0.y;
        }
    }

    __half2* o = (__half2*)(out + (size_t)v * D + lane * (VH * 2));
#pragma unroll
    for (int j = 0; j < VH; j++)
        o[j] = __floats2half2_rn(a[j].x, a[j].y);
}

// ---------------- fp16 tensor-core GEMM, cp.async + ldmatrix ----------------
// C[M,256] = act(A[M,K] @ Wt^T + bias) [* mask[row]]
// A: [M][K] half (row-major). Wt: [256][K] half (n-major).
template <bool RELU, bool MASK, bool HALF_OUT>
__global__ void __launch_bounds__(256, 2)
k_gemm_h(const __half* __restrict__ A, const __half* __restrict__ Wt,
         const float* __restrict__ bias, const float* __restrict__ mask,
         void* __restrict__ Cout, int M, int K) {
    __shared__ __half As[2][128][40];   // [m][k], 80B rows -> conflict-free
    __shared__ __half Bs[2][128][40];   // [n][k]

    int tid  = threadIdx.x;
    int wid  = tid >> 5;
    int lane = tid & 31;
    int g    = lane >> 2;           // 0..7
    int tig  = lane & 3;            // 0..3
    int warp_m = wid & 1;
    int warp_n = wid >> 1;
    int brow = blockIdx.y * 128;
    int bcol = blockIdx.x * 128;

    float acc[4][4][4];
#pragma unroll
    for (int i = 0; i < 4; i++)
#pragma unroll
        for (int j = 0; j < 4; j++)
#pragma unroll
            for (int l = 0; l < 4; l++) acc[i][j][l] = 0.f;

    int lr  = tid >> 2;             // 0..63 (+64 on l=1)
    int lc8 = (tid & 3) << 3;       // k-offset 0,8,16,24 halves

    auto load_tiles = [&](int s, int k0) {
#pragma unroll
        for (int l = 0; l < 2; l++) {
            int r = lr + l * 64;
            int row = brow + r;
            cp16(smem_u32(&As[s][r][lc8]),
                 A + (size_t)row * K + k0 + lc8, row < M ? 16 : 0);
            cp16(smem_u32(&Bs[s][r][lc8]),
                 Wt + (size_t)(bcol + r) * K + k0 + lc8, 16);
        }
        asm volatile("cp.async.commit_group;");
    };

    int a_r  = lane & 15;
    int a_c8 = (lane & 16) >> 1;
    int b_r  = ((lane & 16) >> 1) + (lane & 7);
    int b_c8 = lane & 8;

    load_tiles(0, 0);
    int s = 0;
    for (int k0 = 0; k0 < K; k0 += 32) {
        if (k0 + 32 < K) load_tiles(s ^ 1, k0 + 32);
        else             asm volatile("cp.async.commit_group;");
        asm volatile("cp.async.wait_group 1;");
        __syncthreads();

#pragma unroll
        for (int ks = 0; ks < 32; ks += 16) {
            uint32_t af[4][4], bf[4][2];
#pragma unroll
            for (int mf = 0; mf < 4; mf++) {
                int m0 = warp_m * 64 + mf * 16;
                ldmx4(af[mf], smem_u32(&As[s][m0 + a_r][ks + a_c8]));
            }
#pragma unroll
            for (int p = 0; p < 2; p++) {
                int n0 = warp_n * 32 + p * 16;
                uint32_t br[4];
                ldmx4(br, smem_u32(&Bs[s][n0 + b_r][ks + b_c8]));
                bf[2 * p][0] = br[0]; bf[2 * p][1] = br[1];
                bf[2 * p + 1][0] = br[2]; bf[2 * p + 1][1] = br[3];
            }
#pragma unroll
            for (int mf = 0; mf < 4; mf++)
#pragma unroll
                for (int nf = 0; nf < 4; nf++)
                    mma_f16(acc[mf][nf], af[mf], bf[nf]);
        }
        __syncthreads();
        s ^= 1;
    }

#pragma unroll
    for (int mf = 0; mf < 4; mf++) {
        int row0 = brow + warp_m * 64 + mf * 16 + g;
        int row1 = row0 + 8;
        float mk0 = 1.f, mk1 = 1.f;
        if (MASK) {
            if (row0 < M) mk0 = mask[row0];
            if (row1 < M) mk1 = mask[row1];
        }
#pragma unroll
        for (int nf = 0; nf < 4; nf++) {
            int col = bcol + warp_n * 32 + nf * 8 + tig * 2;
            float2 bb = *(const float2*)(bias + col);
            float v0 = acc[mf][nf][0] + bb.x;
            float v1 = acc[mf][nf][1] + bb.y;
            float v2 = acc[mf][nf][2] + bb.x;
            float v3 = acc[mf][nf][3] + bb.y;
            if (RELU) {
                v0 = fmaxf(v0, 0.f); v1 = fmaxf(v1, 0.f);
                v2 = fmaxf(v2, 0.f); v3 = fmaxf(v3, 0.f);
            }
            if (HALF_OUT) {
                __half* C = (__half*)Cout;
                if (row0 < M)
                    *(__half2*)(C + (size_t)row0 * 256 + col) = __floats2half2_rn(v0, v1);
                if (row1 < M)
                    *(__half2*)(C + (size_t)row1 * 256 + col) = __floats2half2_rn(v2, v3);
            } else {
                float* C = (float*)Cout;
                if (row0 < M)
                    *(float2*)(C + (size_t)row0 * 256 + col) = make_float2(v0 * mk0, v1 * mk0);
                if (row1 < M)
                    *(float2*)(C + (size_t)row1 * 256 + col) = make_float2(v2 * mk1, v3 * mk1);
            }
        }
    }
}

// ---------------- global mean pool (batch sorted): block per graph ----------
__global__ void __launch_bounds__(256)
k_pool2(const int* __restrict__ batch, const __half* __restrict__ h) {
    int gph = blockIdx.x;
    __shared__ int s_lo, s_hi;
    if (threadIdx.x == 0) {
        int lo = 0, hi = NN;
        while (lo < hi) { int mid = (lo + hi) >> 1; if (batch[mid] < gph) lo = mid + 1; else hi = mid; }
        s_lo = lo;
    }
    if (threadIdx.x == 1) {
        int lo = 0, hi = NN;
        while (lo < hi) { int mid = (lo + hi) >> 1; if (batch[mid] < gph + 1) lo = mid + 1; else hi = mid; }
        s_hi = lo;
    }
    __syncthreads();
    int lo = s_lo, hi = s_hi;
    float acc = 0.f;
    for (int v = lo; v < hi; v++)
        acc += __half2float(h[(size_t)v * 256 + threadIdx.x]);
    g_poolh[(size_t)gph * 256 + threadIdx.x] =
        __float2half(acc / fmaxf((float)(hi - lo), 1.f));
    if (threadIdx.x == 0) g_maskf[gph] = (hi > lo) ? 1.f : 0.f;
}

// ---------------- launch ----------------------------------------------------
extern "C" void kernel_launch(void* const* d_in, const int* in_sizes, int n_in,
                              void* d_out, int out_size) {
    const float* x     = (const float*)d_in[0];
    const float* W1    = (const float*)d_in[1];
    const float* b1    = (const float*)d_in[2];
    const float* W2    = (const float*)d_in[3];
    const float* b2    = (const float*)d_in[4];
    const float* W3    = (const float*)d_in[5];
    const float* b3    = (const float*)d_in[6];
    const int*   ei    = (const int*)d_in[7];
    const int*   batch = (const int*)d_in[8];
    float*       out   = (float*)d_out;

    __half *hA, *hB, *xh, *w1h, *w2h, *w3h, *poolh;
    float  *maskb;
    cudaGetSymbolAddress((void**)&hA,    g_bufAh);
    cudaGetSymbolAddress((void**)&hB,    g_bufBh);
    cudaGetSymbolAddress((void**)&xh,    g_xh);
    cudaGetSymbolAddress((void**)&w1h,   g_w1h);
    cudaGetSymbolAddress((void**)&w2h,   g_w2h);
    cudaGetSymbolAddress((void**)&w3h,   g_w3h);
    cudaGetSymbolAddress((void**)&poolh, g_poolh);
    cudaGetSymbolAddress((void**)&maskb, g_maskf);

    dim3 blk(256);
    int gN = (NN + 255) / 256;
    int gE = (EE + 255) / 256;

    // fused prep (cvt x, transpose+cvt weights, degree hist) + CSR build
    k_prep<<<(PREP_T + 255) / 256, blk>>>(x, W1, W2, W3, ei);
    k_scan1<<<NB_SCAN, SCAN_BLK>>>();
    k_scan2<<<1, 128>>>();
    k_scan3<<<gN, blk>>>();
    k_fill<<<gE, blk>>>(ei);

    dim3 ggrid(2, (NN + 127) / 128);
    dim3 ggrid3(2, GG / 128);
    int gAgg = (NN * 32 + 255) / 256;

    // layer 1: agg in 128-dim (half), GEMM(+bias+relu) -> half
    k_agg_h<128><<<gAgg, 256>>>(xh, hA);
    k_gemm_h<true, false, true><<<ggrid, 256>>>(hA, w1h, b1, nullptr, hB, NN, IN_DIM);

    // layer 2
    k_agg_h<256><<<gAgg, 256>>>(hB, hA);
    k_gemm_h<true, false, true><<<ggrid, 256>>>(hA, w2h, b2, nullptr, hB, NN, HID);

    // layer 3: agg, pool (linear), tiny GEMM on pooled [G,256] -> float out
    k_agg_h<256><<<gAgg, 256>>>(hB, hA);
    k_pool2<<<GG, 256>>>(batch, hA);
    k_gemm_h<false, true, false><<<ggrid3, 256>>>(poolh, w3h, b3, maskb, out, GG, HID);
}